// round 14
// baseline (speedup 1.0000x reference)
#include <cuda_runtime.h>
#include <cuda_fp16.h>
#include <math.h>

#define T_TOK 4096
#define C_DIM 256
#define C3    768
#define FF    1024
#define HEADS 8
#define HD    32
#define EPS   1e-5f
#define KVS   4

#if defined(__CUDA_ARCH__) && (__CUDA_ARCH__ >= 900)
#define GRID_DEP_SYNC() cudaGridDependencySynchronize()
#else
#define GRID_DEP_SYNC()
#endif

// ---------------- scratch (device globals; no allocation) ----------------
__device__ __half g_tok0h[T_TOK * C_DIM];
__device__ float  g_tok  [T_TOK * C_DIM];
__device__ __half g_yh   [T_TOK * C_DIM];
__device__ float  g_y32  [T_TOK * C_DIM];
__device__ __half g_qkvh [T_TOK * C3];
__device__ __half g_ovh  [T_TOK * C_DIM];
__device__ float  g_tok2 [T_TOK * C_DIM];
__device__ __half g_zh   [T_TOK * C_DIM];
__device__ __half g_h1h  [T_TOK * FF];
__device__ __half g_tok3h[T_TOK * C_DIM];
__device__ float  g_opart[KVS * T_TOK * C_DIM];
__device__ float  g_l    [KVS * T_TOK * HEADS];
__device__ __half g_w_in_h [C_DIM * C_DIM];
__device__ __half g_w_qkv_h[C3 * C_DIM];
__device__ __half g_w_ap_h [C_DIM * C_DIM];
__device__ __half g_w_ff1_h[FF * C_DIM];
__device__ __half g_w_ff2_h[C_DIM * FF];
__device__ __half g_w_out_h[C_DIM * C_DIM];

// ---------------- helpers ----------------
__device__ __forceinline__ unsigned pack_h2(float lo, float hi) {
    __half2 t = __floats2half2_rn(lo, hi);
    return *reinterpret_cast<unsigned*>(&t);
}
__device__ __forceinline__ unsigned ex2_h2(unsigned x) {
    unsigned y;
    asm("ex2.approx.f16x2 %0, %1;" : "=r"(y) : "r"(x));
    return y;
}
__device__ __forceinline__ void mma_f16(float c[4], const unsigned a[4], const unsigned b[2]) {
    asm volatile(
        "mma.sync.aligned.m16n8k16.row.col.f32.f16.f16.f32 "
        "{%0,%1,%2,%3}, {%4,%5,%6,%7}, {%8,%9}, {%0,%1,%2,%3};"
        : "+f"(c[0]), "+f"(c[1]), "+f"(c[2]), "+f"(c[3])
        : "r"(a[0]), "r"(a[1]), "r"(a[2]), "r"(a[3]), "r"(b[0]), "r"(b[1]));
}
__device__ __forceinline__ void ldsm4(unsigned& r0, unsigned& r1, unsigned& r2, unsigned& r3,
                                      const void* p) {
    unsigned a = (unsigned)__cvta_generic_to_shared(p);
    asm volatile("ldmatrix.sync.aligned.m8n8.x4.shared.b16 {%0,%1,%2,%3}, [%4];"
                 : "=r"(r0), "=r"(r1), "=r"(r2), "=r"(r3) : "r"(a));
}
__device__ __forceinline__ void ldsm4t(unsigned& r0, unsigned& r1, unsigned& r2, unsigned& r3,
                                       const void* p) {
    unsigned a = (unsigned)__cvta_generic_to_shared(p);
    asm volatile("ldmatrix.sync.aligned.m8n8.x4.trans.shared.b16 {%0,%1,%2,%3}, [%4];"
                 : "=r"(r0), "=r"(r1), "=r"(r2), "=r"(r3) : "r"(a));
}
__device__ __forceinline__ void cp16(void* s, const void* g) {
    unsigned sa = (unsigned)__cvta_generic_to_shared(s);
    asm volatile("cp.async.cg.shared.global [%0], [%1], 16;\n" :: "r"(sa), "l"(g));
}
#define CP_COMMIT() asm volatile("cp.async.commit_group;\n" ::: "memory")
#define CP_WAIT2()  asm volatile("cp.async.wait_group 2;\n" ::: "memory")
#define CP_WAIT1()  asm volatile("cp.async.wait_group 1;\n" ::: "memory")
#define CP_WAIT0()  asm volatile("cp.async.wait_group 0;\n" ::: "memory")
__device__ __forceinline__ void cp_wait_dyn(int rem) {
    if (rem >= 2) CP_WAIT2();
    else if (rem == 1) CP_WAIT1();
    else CP_WAIT0();
}

// ---------------- prep: weight cvt + BN-transpose in ONE launch --------------
struct CvtArgs {
    const float* src[6];
    __half* dst[6];
    int n4[6];
};
#define BN_BLOCKS ((C_DIM / 32) * (T_TOK / 32))   // 1024
#define CVT_BLOCKS 448
__global__ void prep_k(CvtArgs a,
                       const float* __restrict__ x,
                       const float* __restrict__ gamma,
                       const float* __restrict__ beta,
                       const float* __restrict__ mean,
                       const float* __restrict__ var,
                       __half* __restrict__ tok0) {
    GRID_DEP_SYNC();
    __shared__ float sm[32][33];
    int bid = blockIdx.x;
    int tid = threadIdx.x;
    if (bid < BN_BLOCKS) {
        int c0 = (bid & 7) * 32, t0 = (bid >> 3) * 32;
        int tx = tid & 31, tw = tid >> 5;
#pragma unroll
        for (int i = 0; i < 4; i++) {
            int ty = tw + i * 8;
            int c = c0 + ty;
            float av = gamma[c] * rsqrtf(var[c] + EPS);
            float bv = beta[c] - mean[c] * av;
            sm[ty][tx] = x[c * T_TOK + t0 + tx] * av + bv;
        }
        __syncthreads();
#pragma unroll
        for (int i = 0; i < 4; i++) {
            int ty = tw + i * 8;
            tok0[(t0 + ty) * C_DIM + c0 + tx] = __float2half(sm[tx][ty]);
        }
    } else {
        int vb = bid - BN_BLOCKS;
#pragma unroll
        for (int s = 0; s < 6; s++) {
            const float4* sp = reinterpret_cast<const float4*>(a.src[s]);
            unsigned* dp = reinterpret_cast<unsigned*>(a.dst[s]);
            int n = a.n4[s];
            for (int i = vb * 256 + tid; i < n; i += CVT_BLOCKS * 256) {
                float4 v = sp[i];
                dp[i * 2 + 0] = pack_h2(v.x, v.y);
                dp[i * 2 + 1] = pack_h2(v.z, v.w);
            }
        }
    }
}

// ---------------- standard fp16 GEMM, BM=64 BN=64 BK=32, 4-stage ring -------
#define GROW 40
#define GSTAGE (128 * GROW)
#define SMEM_GEMM (4 * GSTAGE * 2)
__global__ __launch_bounds__(256, 2)
void gemm_k(const __half* __restrict__ A, const __half* __restrict__ W,
            const float* __restrict__ bias,
            const float* __restrict__ add1, const float* __restrict__ add2,
            float* __restrict__ outf, __half* __restrict__ outh,
            int M, int N, int K, int act) {
    GRID_DEP_SYNC();
    extern __shared__ __half smh[];
    const int tid = threadIdx.x;
    const int warp = tid >> 5, l = tid & 31;
    const int wm = warp >> 1, wn = warp & 1;
    const int r = l >> 2, c2 = (l & 3) * 2;
    const int sub = l & 7, gq = l >> 3;
    const int m0 = blockIdx.y * 64, n0 = blockIdx.x * 64;
    const int lrow = tid >> 2, lch = (tid & 3) * 8;

    float acc[4][4];
#pragma unroll
    for (int j = 0; j < 4; j++)
#pragma unroll
        for (int i = 0; i < 4; i++) acc[j][i] = 0.f;

    const int nt = K >> 5;
#pragma unroll
    for (int t0 = 0; t0 < 3; t0++) {
        if (t0 < nt) {
            __half* As = smh + t0 * GSTAGE;
            __half* Ws = As + 64 * GROW;
            cp16(&As[lrow * GROW + lch], A + (size_t)(m0 + lrow) * K + t0 * 32 + lch);
            cp16(&Ws[lrow * GROW + lch], W + (size_t)(n0 + lrow) * K + t0 * 32 + lch);
            CP_COMMIT();
        }
    }

    for (int t = 0; t < nt; t++) {
        cp_wait_dyn(nt - t - 1);
        __syncthreads();
        __half* As = smh + (t & 3) * GSTAGE;
        __half* Ws = As + 64 * GROW;
#pragma unroll
        for (int kk = 0; kk < 2; kk++) {
            unsigned au[4], bu[4][2];
            const __half* pa = &As[(wm * 16 + (gq & 1) * 8 + sub) * GROW
                                   + kk * 16 + (gq >> 1) * 8];
            ldsm4(au[0], au[1], au[2], au[3], pa);
#pragma unroll
            for (int jp = 0; jp < 2; jp++) {
                const __half* pb = &Ws[(wn * 32 + jp * 16 + (gq >> 1) * 8 + sub) * GROW
                                       + kk * 16 + (gq & 1) * 8];
                ldsm4(bu[2 * jp][0], bu[2 * jp][1], bu[2 * jp + 1][0], bu[2 * jp + 1][1], pb);
            }
#pragma unroll
            for (int j = 0; j < 4; j++)
                mma_f16(acc[j], au, bu[j]);
        }
        if (t + 3 < nt) {
            __half* Asn = smh + ((t + 3) & 3) * GSTAGE;
            __half* Wsn = Asn + 64 * GROW;
            int k0 = (t + 3) * 32;
            cp16(&Asn[lrow * GROW + lch], A + (size_t)(m0 + lrow) * K + k0 + lch);
            cp16(&Wsn[lrow * GROW + lch], W + (size_t)(n0 + lrow) * K + k0 + lch);
            CP_COMMIT();
        }
    }

#pragma unroll
    for (int j = 0; j < 4; j++) {
        int rr0 = m0 + wm * 16 + r;
        int cc = n0 + wn * 32 + 8 * j + c2;
#pragma unroll
        for (int half = 0; half < 2; half++) {
            int rr = rr0 + half * 8;
            float v0 = acc[j][half * 2 + 0] + bias[cc];
            float v1 = acc[j][half * 2 + 1] + bias[cc + 1];
            size_t idx = (size_t)rr * N + cc;
            if (add1) { v0 += add1[idx]; v1 += add1[idx + 1]; }
            if (add2) { v0 += add2[idx]; v1 += add2[idx + 1]; }
            if (act == 1) {
                v0 = 0.5f * v0 * (1.0f + erff(v0 * 0.70710678118654752f));
                v1 = 0.5f * v1 * (1.0f + erff(v1 * 0.70710678118654752f));
            }
            if (outf) { outf[idx] = v0; outf[idx + 1] = v1; }
            if (outh) *reinterpret_cast<unsigned*>(outh + idx) = pack_h2(v0, v1);
        }
    }
}

// ---------------- LN-fused GEMM: BM=16, BN=256(full row), K=256 --------------
// grid M/16=256 blocks, 256 threads (8 warps: wn=warp 0..7, warp tile 16x32).
#define LSTAGE ((16 + 256) * GROW)          // halves per stage
#define SMEM_LN (4 * LSTAGE * 2)            // 87040 bytes
__global__ __launch_bounds__(256)
void gemm_ln_k(const __half* __restrict__ A, const __half* __restrict__ W,
               const float* __restrict__ bias,
               const float* __restrict__ add1, const float* __restrict__ add2,
               const float* __restrict__ lng, const float* __restrict__ lnb,
               float* __restrict__ out_pre,
               __half* __restrict__ out_lnh, float* __restrict__ out_lnf,
               int M, int K) {
    GRID_DEP_SYNC();
    extern __shared__ __half smh[];
    const int tid = threadIdx.x;
    const int wn = tid >> 5, l = tid & 31;
    const int r = l >> 2, c2 = (l & 3) * 2;
    const int sub = l & 7, gq = l >> 3;
    const int m0 = blockIdx.x * 16;

    float acc[4][4];
#pragma unroll
    for (int j = 0; j < 4; j++)
#pragma unroll
        for (int i = 0; i < 4; i++) acc[j][i] = 0.f;

    const int nt = K >> 5;   // 8
#pragma unroll
    for (int t0 = 0; t0 < 3; t0++) {
        __half* As = smh + t0 * LSTAGE;
        __half* Ws = As + 16 * GROW;
        if (tid < 64) {
            int row = tid >> 2, ch = (tid & 3) * 8;
            cp16(&As[row * GROW + ch], A + (size_t)(m0 + row) * K + t0 * 32 + ch);
        }
#pragma unroll
        for (int i = 0; i < 4; i++) {
            int row = (tid >> 2) + i * 64, ch = (tid & 3) * 8;
            cp16(&Ws[row * GROW + ch], W + (size_t)row * K + t0 * 32 + ch);
        }
        CP_COMMIT();
    }

    for (int t = 0; t < nt; t++) {
        cp_wait_dyn(nt - t - 1);
        __syncthreads();
        __half* As = smh + (t & 3) * LSTAGE;
        __half* Ws = As + 16 * GROW;
#pragma unroll
        for (int kk = 0; kk < 2; kk++) {
            unsigned au[4], bu[4][2];
            const __half* pa = &As[((gq & 1) * 8 + sub) * GROW + kk * 16 + (gq >> 1) * 8];
            ldsm4(au[0], au[1], au[2], au[3], pa);
#pragma unroll
            for (int jp = 0; jp < 2; jp++) {
                const __half* pb = &Ws[(wn * 32 + jp * 16 + (gq >> 1) * 8 + sub) * GROW
                                       + kk * 16 + (gq & 1) * 8];
                ldsm4(bu[2 * jp][0], bu[2 * jp][1], bu[2 * jp + 1][0], bu[2 * jp + 1][1], pb);
            }
#pragma unroll
            for (int j = 0; j < 4; j++)
                mma_f16(acc[j], au, bu[j]);
        }
        if (t + 3 < nt) {
            __half* Asn = smh + ((t + 3) & 3) * LSTAGE;
            __half* Wsn = Asn + 16 * GROW;
            int k0 = (t + 3) * 32;
            if (tid < 64) {
                int row = tid >> 2, ch = (tid & 3) * 8;
                cp16(&Asn[row * GROW + ch], A + (size_t)(m0 + row) * K + k0 + ch);
            }
#pragma unroll
            for (int i = 0; i < 4; i++) {
                int row = (tid >> 2) + i * 64, ch = (tid & 3) * 8;
                cp16(&Wsn[row * GROW + ch], W + (size_t)row * K + k0 + ch);
            }
            CP_COMMIT();
        }
    }
    __syncthreads();   // ring reads done; smem reused for LN reduction

    float2* red = reinterpret_cast<float2*>(smh);   // [16 rows][8 warps]
    float s[2] = {0.f, 0.f}, q[2] = {0.f, 0.f};
#pragma unroll
    for (int j = 0; j < 4; j++) {
        int cc = wn * 32 + 8 * j + c2;
#pragma unroll
        for (int half = 0; half < 2; half++) {
            int rg = m0 + r + half * 8;
            size_t idx = (size_t)rg * C_DIM + cc;
            float v0 = acc[j][half * 2 + 0] + bias[cc];
            float v1 = acc[j][half * 2 + 1] + bias[cc + 1];
            if (add1) { v0 += add1[idx]; v1 += add1[idx + 1]; }
            if (add2) { v0 += add2[idx]; v1 += add2[idx + 1]; }
            if (out_pre) *reinterpret_cast<float2*>(out_pre + idx) = make_float2(v0, v1);
            acc[j][half * 2 + 0] = v0; acc[j][half * 2 + 1] = v1;
            s[half] += v0 + v1;
            q[half] += v0 * v0 + v1 * v1;
        }
    }
#pragma unroll
    for (int off = 1; off <= 2; off <<= 1) {
        s[0] += __shfl_xor_sync(0xffffffffu, s[0], off);
        q[0] += __shfl_xor_sync(0xffffffffu, q[0], off);
        s[1] += __shfl_xor_sync(0xffffffffu, s[1], off);
        q[1] += __shfl_xor_sync(0xffffffffu, q[1], off);
    }
    if ((l & 3) == 0) {
        red[r * 8 + wn]       = make_float2(s[0], q[0]);
        red[(r + 8) * 8 + wn] = make_float2(s[1], q[1]);
    }
    __syncthreads();
    float mu[2], rs[2];
#pragma unroll
    for (int half = 0; half < 2; half++) {
        int rl = r + half * 8;
        float ss = 0.f, qq = 0.f;
#pragma unroll
        for (int w8 = 0; w8 < 8; w8++) {
            float2 e = red[rl * 8 + w8];
            ss += e.x; qq += e.y;
        }
        float m = ss * (1.f / C_DIM);
        mu[half] = m;
        rs[half] = rsqrtf(qq * (1.f / C_DIM) - m * m + EPS);
    }
#pragma unroll
    for (int j = 0; j < 4; j++) {
        int cc = wn * 32 + 8 * j + c2;
        float2 g2 = *reinterpret_cast<const float2*>(lng + cc);
        float2 b2 = *reinterpret_cast<const float2*>(lnb + cc);
#pragma unroll
        for (int half = 0; half < 2; half++) {
            int rg = m0 + r + half * 8;
            size_t idx = (size_t)rg * C_DIM + cc;
            float o0 = (acc[j][half * 2 + 0] - mu[half]) * rs[half] * g2.x + b2.x;
            float o1 = (acc[j][half * 2 + 1] - mu[half]) * rs[half] * g2.y + b2.y;
            *reinterpret_cast<unsigned*>(out_lnh + idx) = pack_h2(o0, o1);
            if (out_lnf) *reinterpret_cast<float2*>(out_lnf + idx) = make_float2(o0, o1);
        }
    }
}

// ---------------- proj_out GEMM + transposed write + image residual ----------
#define TSTRIDE 68
__global__ __launch_bounds__(256, 2)
void gemm_out_k(const __half* __restrict__ A, const __half* __restrict__ W,
                const float* __restrict__ bias,
                const float* __restrict__ xin, float* __restrict__ out,
                int K) {
    GRID_DEP_SYNC();
    extern __shared__ __half smh[];
    const int tid = threadIdx.x;
    const int warp = tid >> 5, l = tid & 31;
    const int wm = warp >> 1, wn = warp & 1;
    const int r = l >> 2, c2 = (l & 3) * 2;
    const int sub = l & 7, gq = l >> 3;
    const int m0 = blockIdx.y * 64, n0 = blockIdx.x * 64;
    const int lrow = tid >> 2, lch = (tid & 3) * 8;

    float acc[4][4];
#pragma unroll
    for (int j = 0; j < 4; j++)
#pragma unroll
        for (int i = 0; i < 4; i++) acc[j][i] = 0.f;

    const int nt = K >> 5;
#pragma unroll
    for (int t0 = 0; t0 < 3; t0++) {
        if (t0 < nt) {
            __half* As = smh + t0 * GSTAGE;
            __half* Ws = As + 64 * GROW;
            cp16(&As[lrow * GROW + lch], A + (size_t)(m0 + lrow) * K + t0 * 32 + lch);
            cp16(&Ws[lrow * GROW + lch], W + (size_t)(n0 + lrow) * K + t0 * 32 + lch);
            CP_COMMIT();
        }
    }
    for (int t = 0; t < nt; t++) {
        cp_wait_dyn(nt - t - 1);
        __syncthreads();
        __half* As = smh + (t & 3) * GSTAGE;
        __half* Ws = As + 64 * GROW;
#pragma unroll
        for (int kk = 0; kk < 2; kk++) {
            unsigned au[4], bu[4][2];
            const __half* pa = &As[(wm * 16 + (gq & 1) * 8 + sub) * GROW
                                   + kk * 16 + (gq >> 1) * 8];
            ldsm4(au[0], au[1], au[2], au[3], pa);
#pragma unroll
            for (int jp = 0; jp < 2; jp++) {
                const __half* pb = &Ws[(wn * 32 + jp * 16 + (gq >> 1) * 8 + sub) * GROW
                                       + kk * 16 + (gq & 1) * 8];
                ldsm4(bu[2 * jp][0], bu[2 * jp][1], bu[2 * jp + 1][0], bu[2 * jp + 1][1], pb);
            }
#pragma unroll
            for (int j = 0; j < 4; j++)
                mma_f16(acc[j], au, bu[j]);
        }
        if (t + 3 < nt) {
            __half* Asn = smh + ((t + 3) & 3) * GSTAGE;
            __half* Wsn = Asn + 64 * GROW;
            int k0 = (t + 3) * 32;
            cp16(&Asn[lrow * GROW + lch], A + (size_t)(m0 + lrow) * K + k0 + lch);
            cp16(&Wsn[lrow * GROW + lch], W + (size_t)(n0 + lrow) * K + k0 + lch);
            CP_COMMIT();
        }
    }
    __syncthreads();
    float* tsm = reinterpret_cast<float*>(smh);
#pragma unroll
    for (int j = 0; j < 4; j++) {
        int ccl = wn * 32 + 8 * j + c2;
#pragma unroll
        for (int half = 0; half < 2; half++) {
            int rrl = wm * 16 + r + half * 8;
            int cc = n0 + ccl;
            float v0 = acc[j][half * 2 + 0] + bias[cc];
            float v1 = acc[j][half * 2 + 1] + bias[cc + 1];
            tsm[ccl * TSTRIDE + rrl] = v0;
            tsm[(ccl + 1) * TSTRIDE + rrl] = v1;
        }
    }
    __syncthreads();
    {
        int row = tid >> 2;
        int colb = (tid & 3) * 16;
        int c = n0 + row;
#pragma unroll
        for (int i = 0; i < 4; i++) {
            int tcol = colb + i * 4;
            float4 v = *reinterpret_cast<float4*>(&tsm[row * TSTRIDE + tcol]);
            const float4 xr = *reinterpret_cast<const float4*>(xin + (size_t)c * T_TOK + m0 + tcol);
            v.x += xr.x; v.y += xr.y; v.z += xr.z; v.w += xr.w;
            *reinterpret_cast<float4*>(out + (size_t)c * T_TOK + m0 + tcol) = v;
        }
    }
}

// ---------------- flash attention (unchanged) ----------------
#define AROW 40
#define AKV  (64 * AROW)
#define SMEM_ATTN ((128 * AROW + 4 * 2 * AKV) * 2)
__global__ __launch_bounds__(256)
void attn_k(const __half* __restrict__ qkv,
            float* __restrict__ opart, float* __restrict__ lpart) {
    GRID_DEP_SYNC();
    extern __shared__ __half sma[];
    __half* Qb = sma;
    __half* KV = sma + 128 * AROW;

    const int h = blockIdx.y, q0 = blockIdx.x * 128, split = blockIdx.z;
    const int tid = threadIdx.x;
    const int w = tid >> 5, l = tid & 31;
    const int r = l >> 2, c2 = (l & 3) * 2;
    const int sub = l & 7, gq = l >> 3;
    const float K2 = 1.4426950408889634f * 0.17677669529663689f;
    const __half2 K2h = __float2half2_rn(K2);
    const int lrow = tid >> 2, lch = (tid & 3) * 8;

#pragma unroll
    for (int i = 0; i < 2; i++) {
        int s = tid + i * 256;
        int row = s >> 2, ch = (s & 3) * 8;
        uint4 v = *reinterpret_cast<const uint4*>(qkv + (size_t)(q0 + row) * C3 + h * HD + ch);
        __half2* hv = reinterpret_cast<__half2*>(&v);
#pragma unroll
        for (int k = 0; k < 4; k++) hv[k] = __hmul2(hv[k], K2h);
        *reinterpret_cast<uint4*>(&Qb[row * AROW + ch]) = v;
    }

    const int NT = (T_TOK / KVS) / 64;
    const int kb0 = split * NT;
#pragma unroll
    for (int t0 = 0; t0 < 3; t0++) {
        __half* Ks = KV + t0 * 2 * AKV;
        __half* Vs = Ks + AKV;
        const __half* kp = qkv + (size_t)((kb0 + t0) * 64 + lrow) * C3 + C_DIM + h * HD + lch;
        cp16(&Ks[lrow * AROW + lch], kp);
        cp16(&Vs[lrow * AROW + lch], kp + C_DIM);
        CP_COMMIT();
    }
    __syncthreads();
    unsigned aq[2][4];
#pragma unroll
    for (int kk = 0; kk < 2; kk++) {
        const __half* pq = &Qb[(w * 16 + (gq & 1) * 8 + sub) * AROW + kk * 16 + (gq >> 1) * 8];
        ldsm4(aq[kk][0], aq[kk][1], aq[kk][2], aq[kk][3], pq);
    }

    float oa[4][4];
#pragma unroll
    for (int jd = 0; jd < 4; jd++)
#pragma unroll
        for (int i = 0; i < 4; i++) oa[jd][i] = 0.f;
    float l0 = 0.f, l1 = 0.f;

    for (int t = 0; t < NT; t++) {
        cp_wait_dyn(NT - t - 1);
        __syncthreads();
        __half* Ks = KV + (t & 3) * 2 * AKV;
        __half* Vs = Ks + AKV;

        float st[8][4];
#pragma unroll
        for (int j = 0; j < 8; j++)
#pragma unroll
            for (int i = 0; i < 4; i++) st[j][i] = 0.f;
#pragma unroll
        for (int kk = 0; kk < 2; kk++) {
            unsigned bk[8][2];
#pragma unroll
            for (int jp = 0; jp < 4; jp++) {
                const __half* pk = &Ks[(jp * 16 + (gq >> 1) * 8 + sub) * AROW
                                       + kk * 16 + (gq & 1) * 8];
                ldsm4(bk[2 * jp][0], bk[2 * jp][1], bk[2 * jp + 1][0], bk[2 * jp + 1][1], pk);
            }
#pragma unroll
            for (int j = 0; j < 8; j++)
                mma_f16(st[j], aq[kk], bk[j]);
        }
        unsigned pa[8], pb[8];
#pragma unroll
        for (int j = 0; j < 8; j++) {
            pa[j] = ex2_h2(pack_h2(st[j][0], st[j][1]));
            pb[j] = ex2_h2(pack_h2(st[j][2], st[j][3]));
        }
        {
            __half2 sa = *reinterpret_cast<__half2*>(&pa[0]);
            __half2 sb = *reinterpret_cast<__half2*>(&pb[0]);
#pragma unroll
            for (int j = 1; j < 8; j++) {
                sa = __hadd2(sa, *reinterpret_cast<__half2*>(&pa[j]));
                sb = __hadd2(sb, *reinterpret_cast<__half2*>(&pb[j]));
            }
            float2 fa = __half22float2(sa), fb = __half22float2(sb);
            l0 += fa.x + fa.y;
            l1 += fb.x + fb.y;
        }
#pragma unroll
        for (int kk = 0; kk < 4; kk++) {
            unsigned bv[4][2];
#pragma unroll
            for (int jp = 0; jp < 2; jp++) {
                const __half* pv = &Vs[(kk * 16 + (gq & 1) * 8 + sub) * AROW
                                       + jp * 16 + (gq >> 1) * 8];
                ldsm4t(bv[2 * jp][0], bv[2 * jp][1], bv[2 * jp + 1][0], bv[2 * jp + 1][1], pv);
            }
            unsigned ap[4] = { pa[2 * kk], pb[2 * kk], pa[2 * kk + 1], pb[2 * kk + 1] };
#pragma unroll
            for (int jd = 0; jd < 4; jd++)
                mma_f16(oa[jd], ap, bv[jd]);
        }
        if (t + 3 < NT) {
            __half* Ksn = KV + ((t + 3) & 3) * 2 * AKV;
            __half* Vsn = Ksn + AKV;
            const __half* kp = qkv + (size_t)((kb0 + t + 3) * 64 + lrow) * C3 + C_DIM + h * HD + lch;
            cp16(&Ksn[lrow * AROW + lch], kp);
            cp16(&Vsn[lrow * AROW + lch], kp + C_DIM);
            CP_COMMIT();
        }
    }

    l0 += __shfl_xor_sync(0xffffffffu, l0, 1);
    l0 += __shfl_xor_sync(0xffffffffu, l0, 2);
    l1 += __shfl_xor_sync(0xffffffffu, l1, 1);
    l1 += __shfl_xor_sync(0xffffffffu, l1, 2);

    int row0 = q0 + w * 16 + r;
    float* ob = opart + ((size_t)split * T_TOK) * C_DIM;
#pragma unroll
    for (int jd = 0; jd < 4; jd++) {
        int col = h * HD + 8 * jd + c2;
        *reinterpret_cast<float2*>(ob + (size_t)row0 * C_DIM + col) =
            make_float2(oa[jd][0], oa[jd][1]);
        *reinterpret_cast<float2*>(ob + (size_t)(row0 + 8) * C_DIM + col) =
            make_float2(oa[jd][2], oa[jd][3]);
    }
    if ((l & 3) == 0) {
        lpart[((size_t)split * T_TOK + row0) * HEADS + h] = l0;
        lpart[((size_t)split * T_TOK + row0 + 8) * HEADS + h] = l1;
    }
}

// ---------------- combine KV splits -> f16 (vectorized) ----------------
__global__ void attn_combine_k(const float* __restrict__ opart,
                               const float* __restrict__ lpart,
                               __half* __restrict__ ov) {
    GRID_DEP_SYNC();
    int row  = blockIdx.x * 8 + (threadIdx.x >> 5);
    int lane = threadIdx.x & 31;
    int head = lane >> 2;
    int c = lane * 8;
    float lsum = 0.f;
#pragma unroll
    for (int s = 0; s < KVS; s++)
        lsum += lpart[((size_t)s * T_TOK + row) * HEADS + head];
    float o[8] = {0.f, 0.f, 0.f, 0.f, 0.f, 0.f, 0.f, 0.f};
#pragma unroll
    for (int s = 0; s < KVS; s++) {
        const float4* op = reinterpret_cast<const float4*>(
            opart + ((size_t)s * T_TOK + row) * C_DIM + c);
        float4 p0 = op[0], p1 = op[1];
        o[0] += p0.x; o[1] += p0.y; o[2] += p0.z; o[3] += p0.w;
        o[4] += p1.x; o[5] += p1.y; o[6] += p1.z; o[7] += p1.w;
    }
    float inv = 1.f / lsum;
    uint4 ho;
    ho.x = pack_h2(o[0] * inv, o[1] * inv); ho.y = pack_h2(o[2] * inv, o[3] * inv);
    ho.z = pack_h2(o[4] * inv, o[5] * inv); ho.w = pack_h2(o[6] * inv, o[7] * inv);
    *reinterpret_cast<uint4*>(ov + (size_t)row * C_DIM + c) = ho;
}

// ---------------- launch ----------------
template <typename Sym>
static void* dev_ptr(const Sym& sym) {
    void* p = nullptr;
    cudaGetSymbolAddress(&p, sym);
    return p;
}

template <typename... ExpT, typename... ActT>
static void launch_pdl(void (*kern)(ExpT...), dim3 grid, dim3 block, size_t shmem,
                       ActT&&... args) {
    cudaLaunchConfig_t cfg = {};
    cfg.gridDim = grid;
    cfg.blockDim = block;
    cfg.dynamicSmemBytes = shmem;
    cfg.stream = 0;
    cudaLaunchAttribute attr[1];
    attr[0].id = cudaLaunchAttributeProgrammaticStreamSerialization;
    attr[0].val.programmaticStreamSerializationAllowed = 1;
    cfg.attrs = attr;
    cfg.numAttrs = 1;
    cudaLaunchKernelEx(&cfg, kern, static_cast<ActT&&>(args)...);
}

extern "C" void kernel_launch(void* const* d_in, const int* in_sizes, int n_in,
                              void* d_out, int out_size) {
    (void)in_sizes; (void)n_in; (void)out_size;
    const float* x        = (const float*)d_in[0];
    const float* bn_gamma = (const float*)d_in[1];
    const float* bn_beta  = (const float*)d_in[2];
    const float* bn_mean  = (const float*)d_in[3];
    const float* bn_var   = (const float*)d_in[4];
    const float* w_in     = (const float*)d_in[5];
    const float* b_in     = (const float*)d_in[6];
    const float* ln1_g    = (const float*)d_in[7];
    const float* ln1_b    = (const float*)d_in[8];
    const float* w_qkv    = (const float*)d_in[9];
    const float* b_qkv    = (const float*)d_in[10];
    const float* w_ap     = (const float*)d_in[11];
    const float* b_ap     = (const float*)d_in[12];
    const float* ln2_g    = (const float*)d_in[13];
    const float* ln2_b    = (const float*)d_in[14];
    const float* w_ff1    = (const float*)d_in[15];
    const float* b_ff1    = (const float*)d_in[16];
    const float* w_ff2    = (const float*)d_in[17];
    const float* b_ff2    = (const float*)d_in[18];
    const float* w_out    = (const float*)d_in[19];
    const float* b_out    = (const float*)d_in[20];
    float* out = (float*)d_out;

    __half* tok0h = (__half*)dev_ptr(g_tok0h);
    float*  tok   = (float*)dev_ptr(g_tok);
    __half* yh    = (__half*)dev_ptr(g_yh);
    float*  y32   = (float*)dev_ptr(g_y32);
    __half* qkvh  = (__half*)dev_ptr(g_qkvh);
    __half* ovh   = (__half*)dev_ptr(g_ovh);
    float*  tok2  = (float*)dev_ptr(g_tok2);
    __half* zh    = (__half*)dev_ptr(g_zh);
    __half* h1h   = (__half*)dev_ptr(g_h1h);
    __half* tok3h = (__half*)dev_ptr(g_tok3h);
    float*  opart = (float*)dev_ptr(g_opart);
    float*  lpart = (float*)dev_ptr(g_l);
    __half* w_in_h  = (__half*)dev_ptr(g_w_in_h);
    __half* w_qkv_h = (__half*)dev_ptr(g_w_qkv_h);
    __half* w_ap_h  = (__half*)dev_ptr(g_w_ap_h);
    __half* w_ff1_h = (__half*)dev_ptr(g_w_ff1_h);
    __half* w_ff2_h = (__half*)dev_ptr(g_w_ff2_h);
    __half* w_out_h = (__half*)dev_ptr(g_w_out_h);

    static bool attr_set = false;
    if (!attr_set) {
        cudaFuncSetAttribute(gemm_k, cudaFuncAttributeMaxDynamicSharedMemorySize, SMEM_GEMM);
        cudaFuncSetAttribute(gemm_out_k, cudaFuncAttributeMaxDynamicSharedMemorySize, SMEM_GEMM);
        cudaFuncSetAttribute(gemm_ln_k, cudaFuncAttributeMaxDynamicSharedMemorySize, SMEM_LN);
        cudaFuncSetAttribute(attn_k, cudaFuncAttributeMaxDynamicSharedMemorySize, SMEM_ATTN);
        attr_set = true;
    }

    CvtArgs ca;
    ca.src[0] = w_in;  ca.dst[0] = w_in_h;  ca.n4[0] = C_DIM * C_DIM / 4;
    ca.src[1] = w_qkv; ca.dst[1] = w_qkv_h; ca.n4[1] = C3 * C_DIM / 4;
    ca.src[2] = w_ap;  ca.dst[2] = w_ap_h;  ca.n4[2] = C_DIM * C_DIM / 4;
    ca.src[3] = w_ff1; ca.dst[3] = w_ff1_h; ca.n4[3] = FF * C_DIM / 4;
    ca.src[4] = w_ff2; ca.dst[4] = w_ff2_h; ca.n4[4] = C_DIM * FF / 4;
    ca.src[5] = w_out; ca.dst[5] = w_out_h; ca.n4[5] = C_DIM * C_DIM / 4;

    // 1) prep
    launch_pdl(prep_k, dim3(BN_BLOCKS + CVT_BLOCKS), dim3(256), 0,
               ca, x, bn_gamma, bn_beta, bn_mean, bn_var, tok0h);
    // 2) proj_in + LN1 (fused)
    launch_pdl(gemm_ln_k, dim3(T_TOK / 16), dim3(256), (size_t)SMEM_LN,
               (const __half*)tok0h, (const __half*)w_in_h, b_in,
               (const float*)nullptr, (const float*)nullptr, ln1_g, ln1_b,
               tok, yh, y32, T_TOK, C_DIM);
    // 3) QKV
    launch_pdl(gemm_k, dim3(C3 / 64, T_TOK / 64), dim3(256), (size_t)SMEM_GEMM,
               (const __half*)yh, (const __half*)w_qkv_h, b_qkv,
               (const float*)nullptr, (const float*)nullptr,
               (float*)nullptr, qkvh, T_TOK, C3, C_DIM, 0);
    // 4) attention + 5) combine
    launch_pdl(attn_k, dim3(T_TOK / 128, HEADS, KVS), dim3(256), (size_t)SMEM_ATTN,
               (const __half*)qkvh, opart, lpart);
    launch_pdl(attn_combine_k, dim3(T_TOK / 8), dim3(256), 0,
               (const float*)opart, (const float*)lpart, ovh);
    // 6) attn-proj + residuals + LN2 (fused)
    launch_pdl(gemm_ln_k, dim3(T_TOK / 16), dim3(256), (size_t)SMEM_LN,
               (const __half*)ovh, (const __half*)w_ap_h, b_ap,
               (const float*)y32, (const float*)tok, ln2_g, ln2_b,
               tok2, zh, (float*)nullptr, T_TOK, C_DIM);
    // 7) FF1 + gelu
    launch_pdl(gemm_k, dim3(FF / 64, T_TOK / 64), dim3(256), (size_t)SMEM_GEMM,
               (const __half*)zh, (const __half*)w_ff1_h, b_ff1,
               (const float*)nullptr, (const float*)nullptr,
               (float*)nullptr, h1h, T_TOK, FF, C_DIM, 1);
    // 8) FF2 + tok2 residual
    launch_pdl(gemm_k, dim3(C_DIM / 64, T_TOK / 64), dim3(256), (size_t)SMEM_GEMM,
               (const __half*)h1h, (const __half*)w_ff2_h, b_ff2,
               (const float*)tok2, (const float*)nullptr,
               (float*)nullptr, tok3h, T_TOK, C_DIM, FF, 0);
    // 9) proj_out + transpose + image residual (fused)
    launch_pdl(gemm_out_k, dim3(C_DIM / 64, T_TOK / 64), dim3(256), (size_t)SMEM_GEMM,
               (const __half*)tok3h, (const __half*)w_out_h, b_out, x, out, C_DIM);
}